// round 13
// baseline (speedup 1.0000x reference)
#include <cuda_runtime.h>
#include <cuda_fp16.h>
#include <cstdint>

#define B_  32
#define S_  512
#define D_  256
#define F_  256
#define BS_ 16384
#define KK_ 768
#define NCH 12
#define W_TILE 32768               // 256 rows x 128B, pre-swizzled
#define OFF_A   (2*W_TILE)         // 65536: persistent A region, 66 rows x 512B
#define OFF_PAR (OFF_A + 66*512)   // 99328
#define OFF_SUM (OFF_PAR + 8192)   // 107520
#define OFF_SQ  (OFF_SUM + 1024)
#define OFF_LIN (OFF_SQ  + 1024)
#define OFF_MBAR (OFF_LIN + 1024)  // 110592
#define SMEM_TOTAL (OFF_MBAR + 64 + 128)   // 110784 -> 2 CTAs/SM

__device__ char g_w1s[NCH*W_TILE];
__device__ char g_w2s[NCH*W_TILE];
__device__ char g_h1halo[256*1024];        // [bid][2][512B] swizzled rows
__device__ int  g_rowmap[B_*4608];
__device__ int  g_flag[256];               // monotonic per-launch counters

__device__ __forceinline__ uint32_t smem_u32(const void* p) {
    uint32_t a;
    asm("{ .reg .u64 t; cvta.to.shared.u64 t, %1; cvt.u32.u64 %0, t; }" : "=r"(a) : "l"(p));
    return a;
}
#define MBAR_INIT(a, c) asm volatile("mbarrier.init.shared.b64 [%0], %1;" :: "r"((uint32_t)(a)), "r"((uint32_t)(c)) : "memory")
#define MBAR_EXPECT(a, b) asm volatile("mbarrier.arrive.expect_tx.shared.b64 _, [%0], %1;" :: "r"((uint32_t)(a)), "r"((uint32_t)(b)) : "memory")
#define MBAR_ARRIVE(a) asm volatile("mbarrier.arrive.shared.b64 _, [%0];" :: "r"((uint32_t)(a)) : "memory")
#define MBAR_WAIT(a, ph) do { \
    uint32_t _m = (uint32_t)(a), _p = (uint32_t)(ph), _d; \
    asm volatile("{ .reg .pred p; mbarrier.try_wait.parity.acquire.cta.shared::cta.b64 p, [%1], %2; selp.b32 %0, 1, 0, p; }" \
        : "=r"(_d) : "r"(_m), "r"(_p) : "memory"); \
    if (!_d) { asm volatile("{ .reg .pred P1;\nWL_%=:\n" \
        "mbarrier.try_wait.parity.acquire.cta.shared::cta.b64 P1, [%0], %1, 0x989680;\n" \
        "@P1 bra.uni WD_%=;\nbra.uni WL_%=;\nWD_%=:\n}" :: "r"(_m), "r"(_p) : "memory"); } \
} while (0)
__device__ __forceinline__ void bulk_cp(uint32_t dst, const void* src, uint32_t bytes, uint32_t mbar) {
    asm volatile("cp.async.bulk.shared::cta.global.mbarrier::complete_tx::bytes [%0], [%1], %2, [%3];"
        :: "r"(dst), "l"(src), "r"(bytes), "r"(mbar) : "memory");
}
__device__ __forceinline__ void ldsm_x4(uint32_t* r, uint32_t a) {
    asm volatile("ldmatrix.sync.aligned.m8n8.x4.shared.b16 {%0,%1,%2,%3}, [%4];"
        : "=r"(r[0]), "=r"(r[1]), "=r"(r[2]), "=r"(r[3]) : "r"(a));
}
__device__ __forceinline__ void mma_f16(float* d, const uint32_t* a, const uint32_t* b) {
    asm volatile("mma.sync.aligned.m16n8k16.row.col.f32.f16.f16.f32 "
        "{%0,%1,%2,%3}, {%4,%5,%6,%7}, {%8,%9}, {%0,%1,%2,%3};"
        : "+f"(d[0]), "+f"(d[1]), "+f"(d[2]), "+f"(d[3])
        : "r"(a[0]), "r"(a[1]), "r"(a[2]), "r"(a[3]), "r"(b[0]), "r"(b[1]));
}
__device__ __forceinline__ int ld_acq(const int* p) {
    int v; asm volatile("ld.acquire.gpu.global.s32 %0, [%1];" : "=r"(v) : "l"(p)); return v;
}

// ---- prep: weights -> chunked+swizzled ----
__global__ __launch_bounds__(256) void cvt_w_k(const float* __restrict__ w1,
                                               const float* __restrict__ w2) {
    int gid = blockIdx.x * 256 + threadIdx.x;
    int ph = gid >= F_ * KK_;
    int idx = ph ? gid - F_ * KK_ : gid;
    int f = idx / 768, rem = idx - f * 768;
    int tap = rem >> 8, c = rem & 255;
    int kk = tap * 256 + c;
    int chunk = kk >> 6, kc = kk & 63;
    const float* w = ph ? w2 : w1;
    __half hv = __float2half(w[f * 768 + c * 3 + tap]);
    uint32_t byte = (uint32_t)(2 * kc) ^ (uint32_t)((f & 7) << 4);
    *reinterpret_cast<__half*>((ph ? g_w2s : g_w1s)
        + (size_t)chunk * W_TILE + (size_t)f * 128 + byte) = hv;
}

// ---- one conv phase main loop + epilogue (rotating producer) ----
template<int PH>
__device__ __forceinline__ void conv_phase(
    char* smc, uint32_t tiles, const char* Wst,
    int mBase, int bid, int tid, int lane, int warp, int mw, int nw,
    int* pha, const float* par,
    float* sSum, float* sSq, float* sLin,
    float* pred, const float* lbp)
{
    const uint32_t mbF = tiles + OFF_MBAR, mbE = mbF + 16;
    const uint32_t aA = tiles + OFF_A;

    float acc[2][8][4];
    #pragma unroll
    for (int a = 0; a < 2; a++)
        #pragma unroll
        for (int b = 0; b < 8; b++)
            #pragma unroll
            for (int c = 0; c < 4; c++) acc[a][b][c] = 0.f;

    for (int i = 0; i < NCH; i++) {
        const int st = i & 1;
        const int tap = i >> 2;
        const int cg = i & 3;
        // rotating producer: warp (nc&7) lane 0 refills stage nc&1 for chunk nc=i+1
        const int nc = i + 1;
        if (i >= 1 && nc < NCH && warp == (nc & 7) && lane == 0) {
            const int st2 = nc & 1;
            MBAR_WAIT(mbE + 8 * st2, ((nc >> 1) + 1) & 1);
            MBAR_EXPECT(mbF + 8 * st2, W_TILE);
            bulk_cp(tiles + st2 * W_TILE, Wst + (size_t)nc * W_TILE, W_TILE, mbF + 8 * st2);
        }
        MBAR_WAIT(mbF + 8 * st, pha[st]); pha[st] ^= 1;
        const uint32_t wT = tiles + st * W_TILE;

        #pragma unroll
        for (int ks = 0; ks < 4; ks++) {
            uint32_t bf[8][2];
            #pragma unroll
            for (int njp = 0; njp < 4; njp++) {
                int f = nw * 64 + (2 * njp + ((lane >> 4) & 1)) * 8 + (lane & 7);
                int kseg = ks * 2 + ((lane >> 3) & 1);
                uint32_t ad = wT + (uint32_t)f * 128 + (uint32_t)((kseg ^ (f & 7)) << 4);
                uint32_t r[4];
                ldsm_x4(r, ad);
                bf[2 * njp][0] = r[0]; bf[2 * njp][1] = r[1];
                bf[2 * njp + 1][0] = r[2]; bf[2 * njp + 1][1] = r[3];
            }
            #pragma unroll
            for (int mi = 0; mi < 2; mi++) {
                int p = mw * 32 + mi * 16 + (lane & 7) + ((lane >> 3) & 1) * 8 + tap;
                int kseg = ks * 2 + ((lane >> 4) & 1);
                uint32_t ad = aA + (uint32_t)p * 512 + (uint32_t)cg * 128
                              + (uint32_t)((kseg ^ (p & 7)) << 4);
                uint32_t af[4];
                ldsm_x4(af, ad);
                #pragma unroll
                for (int nj = 0; nj < 8; nj++)
                    mma_f16(acc[mi][nj], af, bf[nj]);
            }
        }
        if (lane == 0) MBAR_ARRIVE(mbE + 8 * st);
    }
    __syncthreads();

    // ---- PH=0 hook: drain final empties (6th completion, parity 1), prefetch W2 ----
    if (PH == 0 && tid == 0) {
        MBAR_WAIT(mbE, 1);
        MBAR_WAIT(mbE + 8, 1);
        #pragma unroll
        for (int j = 0; j < 2; j++) {
            MBAR_EXPECT(mbF + 8 * j, W_TILE);
            bulk_cp(tiles + j * W_TILE, g_w2s + (size_t)j * W_TILE, W_TILE, mbF + 8 * j);
        }
    }

    // ---- epilogue: bias + LN ----
    #pragma unroll
    for (int mi = 0; mi < 2; mi++)
        #pragma unroll
        for (int rh = 0; rh < 2; rh++) {
            float s = 0.f, q = 0.f;
            #pragma unroll
            for (int nj = 0; nj < 8; nj++)
                #pragma unroll
                for (int h = 0; h < 2; h++) {
                    int col = nw * 64 + nj * 8 + 2 * (lane & 3) + h;
                    float v = acc[mi][nj][rh * 2 + h] + par[col];
                    acc[mi][nj][rh * 2 + h] = v;
                    s += v; q = fmaf(v, v, q);
                }
            s += __shfl_xor_sync(0xffffffffu, s, 1); s += __shfl_xor_sync(0xffffffffu, s, 2);
            q += __shfl_xor_sync(0xffffffffu, q, 1); q += __shfl_xor_sync(0xffffffffu, q, 2);
            if ((lane & 3) == 0) {
                int r = mw * 32 + mi * 16 + rh * 8 + (lane >> 2);
                sSum[nw * 64 + r] = s; sSq[nw * 64 + r] = q;
            }
        }
    __syncthreads();

    float lacc[2][2];
    #pragma unroll
    for (int mi = 0; mi < 2; mi++)
        #pragma unroll
        for (int rh = 0; rh < 2; rh++) {
            int r = mw * 32 + mi * 16 + rh * 8 + (lane >> 2);
            float tot = sSum[r] + sSum[64 + r] + sSum[128 + r] + sSum[192 + r];
            float tq  = sSq[r]  + sSq[64 + r]  + sSq[128 + r]  + sSq[192 + r];
            float mu = tot * (1.f / 256.f);
            float rstd = rsqrtf(tq * (1.f / 256.f) - mu * mu + 1e-5f);
            const int p = r + 1;
            float la = 0.f;
            #pragma unroll
            for (int nj = 0; nj < 8; nj++) {
                int col0 = nw * 64 + nj * 8 + 2 * (lane & 3);
                float v0 = acc[mi][nj][rh * 2 + 0], v1 = acc[mi][nj][rh * 2 + 1];
                float o0 = fmaxf(0.f, fmaf((v0 - mu) * rstd, par[256 + col0],     par[512 + col0]));
                float o1 = fmaxf(0.f, fmaf((v1 - mu) * rstd, par[256 + col0 + 1], par[512 + col0 + 1]));
                if (PH == 0) {
                    __half2 hxv = __floats2half2_rn(o0, o1);
                    uint32_t hx = *reinterpret_cast<uint32_t*>(&hxv);
                    uint32_t off = (uint32_t)(col0 >> 6) * 128
                                 + (uint32_t)((((col0 >> 3) & 7) ^ (p & 7)) << 4)
                                 + (uint32_t)((col0 & 7) * 2);
                    *reinterpret_cast<uint32_t*>(smc + OFF_A + p * 512 + off) = hx;
                    if (r == 0)
                        *reinterpret_cast<uint32_t*>(g_h1halo + bid * 1024 + off) = hx;
                    if (r == 63)
                        *reinterpret_cast<uint32_t*>(g_h1halo + bid * 1024 + 512 + off) = hx;
                } else {
                    la = fmaf(o0, par[768 + col0], la);
                    la = fmaf(o1, par[768 + col0 + 1], la);
                }
            }
            lacc[mi][rh] = la;
        }

    if (PH == 1) {
        #pragma unroll
        for (int mi = 0; mi < 2; mi++)
            #pragma unroll
            for (int rh = 0; rh < 2; rh++) {
                float la = lacc[mi][rh];
                la += __shfl_xor_sync(0xffffffffu, la, 1);
                la += __shfl_xor_sync(0xffffffffu, la, 2);
                if ((lane & 3) == 0)
                    sLin[nw * 64 + mw * 32 + mi * 16 + rh * 8 + (lane >> 2)] = la;
            }
        __syncthreads();
        if (nw == 0 && (lane & 3) == 0) {
            #pragma unroll
            for (int mi = 0; mi < 2; mi++)
                #pragma unroll
                for (int rh = 0; rh < 2; rh++) {
                    int r = mw * 32 + mi * 16 + rh * 8 + (lane >> 2);
                    float t = sLin[r] + sLin[64 + r] + sLin[128 + r] + sLin[192 + r];
                    pred[mBase + r] = fmaxf(0.f, t + lbp[0]);
                }
        }
    }
}

// ---- fused conv0 + conv1 persistent kernel, in-kernel x conversion ----
__global__ __launch_bounds__(256, 2) void fused_conv_k(
    const float* __restrict__ x,
    const float* __restrict__ b1, const float* __restrict__ g1, const float* __restrict__ be1,
    const float* __restrict__ b2, const float* __restrict__ g2, const float* __restrict__ be2,
    const float* __restrict__ lw, const float* __restrict__ lbp, float* __restrict__ pred)
{
    extern __shared__ char smem[];
    const uint32_t sb0 = smem_u32(smem);
    const uint32_t tiles = (sb0 + 127) & ~127u;
    char* smc = smem + (tiles - sb0);
    float* sPar = (float*)(smc + OFF_PAR);
    float* sSum = (float*)(smc + OFF_SUM);
    float* sSq  = (float*)(smc + OFF_SQ);
    float* sLin = (float*)(smc + OFF_LIN);
    const uint32_t mbF = tiles + OFF_MBAR;
    const int tid = threadIdx.x, lane = tid & 31, warp = tid >> 5;
    const int mw = warp >> 2, nw = warp & 3;
    const int bid = blockIdx.x;
    const int mBase = bid * 64;
    const bool fix0 = ((mBase & 511) == 0);
    const bool fix2 = (((mBase + 64) & 511) == 0);

    int base = 0;
    if (tid == 0) base = g_flag[bid];

    sPar[tid] = b1[tid];        sPar[256 + tid] = g1[tid];
    sPar[512 + tid] = be1[tid]; sPar[768 + tid] = 0.f;
    sPar[1024 + tid] = b2[tid]; sPar[1280 + tid] = g2[tid];
    sPar[1536 + tid] = be2[tid]; sPar[1792 + tid] = lw[tid];
    if (tid == 0) {
        MBAR_INIT(mbF, 1); MBAR_INIT(mbF + 8, 1);
        MBAR_INIT(mbF + 16, 8); MBAR_INIT(mbF + 24, 8);
    }
    __syncthreads();

    // issue W1 chunks 0,1 (overlaps x conversion below)
    if (tid == 0) {
        #pragma unroll
        for (int j = 0; j < 2; j++) {
            MBAR_EXPECT(mbF + 8 * j, W_TILE);
            bulk_cp(tiles + j * W_TILE, g_w1s + (size_t)j * W_TILE, W_TILE, mbF + 8 * j);
        }
    }

    // convert own x rows (with halo) fp32 -> fp16 swizzled into persistent A region
    for (int it = tid; it < 66 * 32; it += 256) {
        int row = it >> 5, s = it & 31;
        bool zero = (row == 0 && fix0) || (row == 65 && fix2);
        float4 v0 = make_float4(0.f, 0.f, 0.f, 0.f), v1 = v0;
        if (!zero) {
            const float4* src = reinterpret_cast<const float4*>(
                x + (size_t)(mBase - 1 + row) * 256 + s * 8);
            v0 = src[0]; v1 = src[1];
        }
        __half2 a = __floats2half2_rn(v0.x, v0.y), b = __floats2half2_rn(v0.z, v0.w);
        __half2 c = __floats2half2_rn(v1.x, v1.y), d = __floats2half2_rn(v1.z, v1.w);
        uint4 o = make_uint4(*(uint32_t*)&a, *(uint32_t*)&b, *(uint32_t*)&c, *(uint32_t*)&d);
        *reinterpret_cast<uint4*>(smc + OFF_A + row * 512 + (s >> 3) * 128
            + (((s & 7) ^ (row & 7)) << 4)) = o;
    }
    __syncthreads();

    int pha[2] = {0, 0};

    // phase 0: x -> h1 (h1 written to smem A region + 2 halo rows to gmem)
    conv_phase<0>(smc, tiles, g_w1s, mBase, bid, tid, lane, warp, mw, nw,
                  pha, sPar, sSum, sSq, sLin, pred, lbp);

    // publish halo rows; wait only for needed neighbors; fill p=0 / p=65
    __threadfence();
    __syncthreads();
    if (tid == 0) {
        atomicExch(&g_flag[bid], base + 1);
        const int tgt = base + 1;
        if (!fix0) while (ld_acq(&g_flag[bid - 1]) != tgt) __nanosleep(32);
        if (!fix2) while (ld_acq(&g_flag[bid + 1]) != tgt) __nanosleep(32);
    }
    __syncthreads();
    if (warp == 0) {
        uint4 v = make_uint4(0, 0, 0, 0);
        if (!fix0) v = *reinterpret_cast<const uint4*>(g_h1halo + (bid - 1) * 1024 + 512 + lane * 16);
        *reinterpret_cast<uint4*>(smc + OFF_A + lane * 16) = v;
    } else if (warp == 1) {
        uint4 v = make_uint4(0, 0, 0, 0);
        if (!fix2) v = *reinterpret_cast<const uint4*>(g_h1halo + (bid + 1) * 1024 + lane * 16);
        *reinterpret_cast<uint4*>(smc + OFF_A + 65 * 512 + lane * 16) = v;
    }
    __syncthreads();

    // phase 1: h1 -> pred
    conv_phase<1>(smc, tiles, g_w2s, mBase, bid, tid, lane, warp, mw, nw,
                  pha, sPar + 1024, sSum, sSq, sLin, pred, lbp);
}

// ---- rowmap + gather (unchanged, proven) ----
__global__ __launch_bounds__(512) void rowmap_k(const float* __restrict__ target, int L) {
    int b = blockIdx.x, s = threadIdx.x;
    int lane = s & 31, wp = s >> 5;
    int d = (int)rintf(target[b * 512 + s]);
    int v = d;
    #pragma unroll
    for (int o = 1; o < 32; o <<= 1) {
        int t = __shfl_up_sync(0xffffffffu, v, o);
        if (lane >= o) v += t;
    }
    __shared__ int wsum[16];
    if (lane == 31) wsum[wp] = v;
    __syncthreads();
    if (s < 16) {
        int w = wsum[s];
        #pragma unroll
        for (int o = 1; o < 16; o <<= 1) {
            int t = __shfl_up_sync(0x0000ffffu, w, o);
            if (s >= o) w += t;
        }
        wsum[s] = w;
    }
    __syncthreads();
    int end = v + (wp ? wsum[wp - 1] : 0);
    int start = end - d;
    int* rm = g_rowmap + (size_t)b * L;
    for (int l = s; l < L; l += 512) rm[l] = -1;
    __syncthreads();
    if (start < L) {
        int e = min(end, L);
        for (int l = start; l < e; ++l) rm[l] = s;
    }
}

__global__ __launch_bounds__(256) void gather_k(const float* __restrict__ x,
                                                float* __restrict__ out, int L) {
    int rowId = blockIdx.x * 4 + (threadIdx.x >> 6);
    if (rowId >= B_ * L) return;
    int t = threadIdx.x & 63;
    int b = rowId / L;
    int s = g_rowmap[rowId];
    float4 v = make_float4(0.f, 0.f, 0.f, 0.f);
    if (s >= 0)
        v = *reinterpret_cast<const float4*>(x + (size_t)((b << 9) + s) * D_ + (t << 2));
    *reinterpret_cast<float4*>(out + (size_t)rowId * D_ + (t << 2)) = v;
}

extern "C" void kernel_launch(void* const* d_in, const int* in_sizes, int n_in,
                              void* d_out, int out_size) {
    const float* x   = (const float*)d_in[0];
    const float* tgt = (const float*)d_in[1];
    const float* c1w = (const float*)d_in[2];
    const float* c1b = (const float*)d_in[3];
    const float* c2w = (const float*)d_in[4];
    const float* c2b = (const float*)d_in[5];
    const float* n1g = (const float*)d_in[6];
    const float* n1b = (const float*)d_in[7];
    const float* n2g = (const float*)d_in[8];
    const float* n2b = (const float*)d_in[9];
    const float* lw  = (const float*)d_in[10];
    const float* lb  = (const float*)d_in[11];

    float* out = (float*)d_out;
    int L = (out_size - B_ * S_) / (B_ * D_);
    float* pred = out + (size_t)B_ * L * D_;

    static cudaStream_t sHi = nullptr, sLo = nullptr;
    static cudaEvent_t evF = nullptr, evH = nullptr, evJ = nullptr;
    if (sHi == nullptr) {
        int pLo, pHi;
        cudaDeviceGetStreamPriorityRange(&pLo, &pHi);
        cudaStreamCreateWithPriority(&sHi, cudaStreamNonBlocking, pHi);
        cudaStreamCreateWithPriority(&sLo, cudaStreamNonBlocking, pLo);
        cudaEventCreateWithFlags(&evF, cudaEventDisableTiming);
        cudaEventCreateWithFlags(&evH, cudaEventDisableTiming);
        cudaEventCreateWithFlags(&evJ, cudaEventDisableTiming);
        cudaFuncSetAttribute(fused_conv_k, cudaFuncAttributeMaxDynamicSharedMemorySize, SMEM_TOTAL);
    }

    // fork
    cudaEventRecord(evF, 0);
    cudaStreamWaitEvent(sHi, evF, 0);
    cudaStreamWaitEvent(sLo, evF, 0);

    // low-priority branch: length regulator
    rowmap_k<<<B_, 512, 0, sLo>>>(tgt, L);
    gather_k<<<(B_ * L + 3) / 4, 256, 0, sLo>>>(x, out, L);
    cudaEventRecord(evJ, sLo);

    // high-priority branch: weight prep + fused duration predictor
    cvt_w_k<<<2 * F_ * KK_ / 256, 256, 0, sHi>>>(c1w, c2w);
    fused_conv_k<<<256, 256, SMEM_TOTAL, sHi>>>(x, c1b, n1g, n1b, c2b, n2g, n2b, lw, lb, pred);
    cudaEventRecord(evH, sHi);

    // join
    cudaStreamWaitEvent(0, evH, 0);
    cudaStreamWaitEvent(0, evJ, 0);
}

// round 14
// speedup vs baseline: 1.2889x; 1.2889x over previous
#include <cuda_runtime.h>
#include <cuda_fp16.h>
#include <cstdint>

#define B_  32
#define S_  512
#define D_  256
#define F_  256
#define BS_ 16384
#define KK_ 768
#define NCH 12
#define W_TILE 32768               // 256 rows x 128B, pre-swizzled
#define OFF_A   (2*W_TILE)         // 65536: persistent A region, 66 rows x 512B
#define OFF_PAR (OFF_A + 66*512)   // 99328
#define OFF_SUM (OFF_PAR + 8192)   // 107520
#define OFF_SQ  (OFF_SUM + 1024)
#define OFF_LIN (OFF_SQ  + 1024)
#define OFF_MBAR (OFF_LIN + 1024)  // 110592
#define SMEM_TOTAL (OFF_MBAR + 64 + 128)   // 110784 -> 2 CTAs/SM

__device__ char g_w1s[NCH*W_TILE];
__device__ char g_w2s[NCH*W_TILE];
__device__ char g_h1halo[256*1024];        // [bid][2][512B] swizzled rows
__device__ int  g_rowmap[B_*4608];
__device__ int  g_flag[256];               // monotonic per-launch counters

__device__ __forceinline__ uint32_t smem_u32(const void* p) {
    uint32_t a;
    asm("{ .reg .u64 t; cvta.to.shared.u64 t, %1; cvt.u32.u64 %0, t; }" : "=r"(a) : "l"(p));
    return a;
}
#define MBAR_INIT(a, c) asm volatile("mbarrier.init.shared.b64 [%0], %1;" :: "r"((uint32_t)(a)), "r"((uint32_t)(c)) : "memory")
#define MBAR_EXPECT(a, b) asm volatile("mbarrier.arrive.expect_tx.shared.b64 _, [%0], %1;" :: "r"((uint32_t)(a)), "r"((uint32_t)(b)) : "memory")
#define MBAR_ARRIVE(a) asm volatile("mbarrier.arrive.shared.b64 _, [%0];" :: "r"((uint32_t)(a)) : "memory")
#define MBAR_WAIT(a, ph) do { \
    uint32_t _m = (uint32_t)(a), _p = (uint32_t)(ph), _d; \
    asm volatile("{ .reg .pred p; mbarrier.try_wait.parity.acquire.cta.shared::cta.b64 p, [%1], %2; selp.b32 %0, 1, 0, p; }" \
        : "=r"(_d) : "r"(_m), "r"(_p) : "memory"); \
    if (!_d) { asm volatile("{ .reg .pred P1;\nWL_%=:\n" \
        "mbarrier.try_wait.parity.acquire.cta.shared::cta.b64 P1, [%0], %1, 0x989680;\n" \
        "@P1 bra.uni WD_%=;\nbra.uni WL_%=;\nWD_%=:\n}" :: "r"(_m), "r"(_p) : "memory"); } \
} while (0)
__device__ __forceinline__ void bulk_cp(uint32_t dst, const void* src, uint32_t bytes, uint32_t mbar) {
    asm volatile("cp.async.bulk.shared::cta.global.mbarrier::complete_tx::bytes [%0], [%1], %2, [%3];"
        :: "r"(dst), "l"(src), "r"(bytes), "r"(mbar) : "memory");
}
__device__ __forceinline__ void ldsm_x4(uint32_t* r, uint32_t a) {
    asm volatile("ldmatrix.sync.aligned.m8n8.x4.shared.b16 {%0,%1,%2,%3}, [%4];"
        : "=r"(r[0]), "=r"(r[1]), "=r"(r[2]), "=r"(r[3]) : "r"(a));
}
__device__ __forceinline__ void mma_f16(float* d, const uint32_t* a, const uint32_t* b) {
    asm volatile("mma.sync.aligned.m16n8k16.row.col.f32.f16.f16.f32 "
        "{%0,%1,%2,%3}, {%4,%5,%6,%7}, {%8,%9}, {%0,%1,%2,%3};"
        : "+f"(d[0]), "+f"(d[1]), "+f"(d[2]), "+f"(d[3])
        : "r"(a[0]), "r"(a[1]), "r"(a[2]), "r"(a[3]), "r"(b[0]), "r"(b[1]));
}
__device__ __forceinline__ int ld_acq(const int* p) {
    int v; asm volatile("ld.acquire.gpu.global.s32 %0, [%1];" : "=r"(v) : "l"(p)); return v;
}

// ---- prep: weights -> chunked+swizzled ----
__global__ __launch_bounds__(256) void cvt_w_k(const float* __restrict__ w1,
                                               const float* __restrict__ w2) {
    int gid = blockIdx.x * 256 + threadIdx.x;
    int ph = gid >= F_ * KK_;
    int idx = ph ? gid - F_ * KK_ : gid;
    int f = idx / 768, rem = idx - f * 768;
    int tap = rem >> 8, c = rem & 255;
    int kk = tap * 256 + c;
    int chunk = kk >> 6, kc = kk & 63;
    const float* w = ph ? w2 : w1;
    __half hv = __float2half(w[f * 768 + c * 3 + tap]);
    uint32_t byte = (uint32_t)(2 * kc) ^ (uint32_t)((f & 7) << 4);
    *reinterpret_cast<__half*>((ph ? g_w2s : g_w1s)
        + (size_t)chunk * W_TILE + (size_t)f * 128 + byte) = hv;
}

// ---- one conv phase main loop + epilogue (producer = warp 7 lane 0) ----
template<int PH>
__device__ __forceinline__ void conv_phase(
    char* smc, uint32_t tiles, const char* Wst,
    int mBase, int bid, int tid, int lane, int mw, int nw,
    int* pha, int* eph, const float* par,
    float* sSum, float* sSq, float* sLin,
    float* pred, const float* lbp)
{
    const uint32_t mbF = tiles + OFF_MBAR, mbE = mbF + 16;
    const uint32_t aA = tiles + OFF_A;
    const bool producer = (tid == 224);        // warp 7 lane 0 (hi-wid arbiter priority)

    float acc[2][8][4];
    #pragma unroll
    for (int a = 0; a < 2; a++)
        #pragma unroll
        for (int b = 0; b < 8; b++)
            #pragma unroll
            for (int c = 0; c < 4; c++) acc[a][b][c] = 0.f;

    for (int i = 0; i < NCH; i++) {
        const int st = i & 1;
        const int tap = i >> 2;
        const int cg = i & 3;
        if (producer && i >= 1 && i + 1 < NCH) {
            const int st2 = st ^ 1;
            MBAR_WAIT(mbE + 8 * st2, eph[st2]); eph[st2] ^= 1;
            MBAR_EXPECT(mbF + 8 * st2, W_TILE);
            bulk_cp(tiles + st2 * W_TILE, Wst + (size_t)(i + 1) * W_TILE, W_TILE, mbF + 8 * st2);
        }
        MBAR_WAIT(mbF + 8 * st, pha[st]); pha[st] ^= 1;
        const uint32_t wT = tiles + st * W_TILE;

        #pragma unroll
        for (int ks = 0; ks < 4; ks++) {
            uint32_t bf[8][2];
            #pragma unroll
            for (int njp = 0; njp < 4; njp++) {
                int f = nw * 64 + (2 * njp + ((lane >> 4) & 1)) * 8 + (lane & 7);
                int kseg = ks * 2 + ((lane >> 3) & 1);
                uint32_t ad = wT + (uint32_t)f * 128 + (uint32_t)((kseg ^ (f & 7)) << 4);
                uint32_t r[4];
                ldsm_x4(r, ad);
                bf[2 * njp][0] = r[0]; bf[2 * njp][1] = r[1];
                bf[2 * njp + 1][0] = r[2]; bf[2 * njp + 1][1] = r[3];
            }
            #pragma unroll
            for (int mi = 0; mi < 2; mi++) {
                int p = mw * 32 + mi * 16 + (lane & 7) + ((lane >> 3) & 1) * 8 + tap;
                int kseg = ks * 2 + ((lane >> 4) & 1);
                uint32_t ad = aA + (uint32_t)p * 512 + (uint32_t)cg * 128
                              + (uint32_t)((kseg ^ (p & 7)) << 4);
                uint32_t af[4];
                ldsm_x4(af, ad);
                #pragma unroll
                for (int nj = 0; nj < 8; nj++)
                    mma_f16(acc[mi][nj], af, bf[nj]);
            }
        }
        if (lane == 0) MBAR_ARRIVE(mbE + 8 * st);
    }
    __syncthreads();

    // ---- PH=0 hook: drain leftover empties, prefetch W2 chunks 0/1 ----
    if (PH == 0 && tid == 224) {
        MBAR_WAIT(mbE, eph[0]); eph[0] ^= 1;
        MBAR_WAIT(mbE + 8, eph[1]); eph[1] ^= 1;
        #pragma unroll
        for (int j = 0; j < 2; j++) {
            MBAR_EXPECT(mbF + 8 * j, W_TILE);
            bulk_cp(tiles + j * W_TILE, g_w2s + (size_t)j * W_TILE, W_TILE, mbF + 8 * j);
        }
    }

    // ---- epilogue: bias + LN ----
    #pragma unroll
    for (int mi = 0; mi < 2; mi++)
        #pragma unroll
        for (int rh = 0; rh < 2; rh++) {
            float s = 0.f, q = 0.f;
            #pragma unroll
            for (int nj = 0; nj < 8; nj++)
                #pragma unroll
                for (int h = 0; h < 2; h++) {
                    int col = nw * 64 + nj * 8 + 2 * (lane & 3) + h;
                    float v = acc[mi][nj][rh * 2 + h] + par[col];
                    acc[mi][nj][rh * 2 + h] = v;
                    s += v; q = fmaf(v, v, q);
                }
            s += __shfl_xor_sync(0xffffffffu, s, 1); s += __shfl_xor_sync(0xffffffffu, s, 2);
            q += __shfl_xor_sync(0xffffffffu, q, 1); q += __shfl_xor_sync(0xffffffffu, q, 2);
            if ((lane & 3) == 0) {
                int r = mw * 32 + mi * 16 + rh * 8 + (lane >> 2);
                sSum[nw * 64 + r] = s; sSq[nw * 64 + r] = q;
            }
        }
    __syncthreads();

    float lacc[2][2];
    #pragma unroll
    for (int mi = 0; mi < 2; mi++)
        #pragma unroll
        for (int rh = 0; rh < 2; rh++) {
            int r = mw * 32 + mi * 16 + rh * 8 + (lane >> 2);
            float tot = sSum[r] + sSum[64 + r] + sSum[128 + r] + sSum[192 + r];
            float tq  = sSq[r]  + sSq[64 + r]  + sSq[128 + r]  + sSq[192 + r];
            float mu = tot * (1.f / 256.f);
            float rstd = rsqrtf(tq * (1.f / 256.f) - mu * mu + 1e-5f);
            const int p = r + 1;
            float la = 0.f;
            #pragma unroll
            for (int nj = 0; nj < 8; nj++) {
                int col0 = nw * 64 + nj * 8 + 2 * (lane & 3);
                float v0 = acc[mi][nj][rh * 2 + 0], v1 = acc[mi][nj][rh * 2 + 1];
                float o0 = fmaxf(0.f, fmaf((v0 - mu) * rstd, par[256 + col0],     par[512 + col0]));
                float o1 = fmaxf(0.f, fmaf((v1 - mu) * rstd, par[256 + col0 + 1], par[512 + col0 + 1]));
                if (PH == 0) {
                    __half2 hxv = __floats2half2_rn(o0, o1);
                    uint32_t hx = *reinterpret_cast<uint32_t*>(&hxv);
                    uint32_t off = (uint32_t)(col0 >> 6) * 128
                                 + (uint32_t)((((col0 >> 3) & 7) ^ (p & 7)) << 4)
                                 + (uint32_t)((col0 & 7) * 2);
                    *reinterpret_cast<uint32_t*>(smc + OFF_A + p * 512 + off) = hx;
                    if (r == 0)
                        *reinterpret_cast<uint32_t*>(g_h1halo + bid * 1024 + off) = hx;
                    if (r == 63)
                        *reinterpret_cast<uint32_t*>(g_h1halo + bid * 1024 + 512 + off) = hx;
                } else {
                    la = fmaf(o0, par[768 + col0], la);
                    la = fmaf(o1, par[768 + col0 + 1], la);
                }
            }
            lacc[mi][rh] = la;
        }

    if (PH == 1) {
        #pragma unroll
        for (int mi = 0; mi < 2; mi++)
            #pragma unroll
            for (int rh = 0; rh < 2; rh++) {
                float la = lacc[mi][rh];
                la += __shfl_xor_sync(0xffffffffu, la, 1);
                la += __shfl_xor_sync(0xffffffffu, la, 2);
                if ((lane & 3) == 0)
                    sLin[nw * 64 + mw * 32 + mi * 16 + rh * 8 + (lane >> 2)] = la;
            }
        __syncthreads();
        if (nw == 0 && (lane & 3) == 0) {
            #pragma unroll
            for (int mi = 0; mi < 2; mi++)
                #pragma unroll
                for (int rh = 0; rh < 2; rh++) {
                    int r = mw * 32 + mi * 16 + rh * 8 + (lane >> 2);
                    float t = sLin[r] + sLin[64 + r] + sLin[128 + r] + sLin[192 + r];
                    pred[mBase + r] = fmaxf(0.f, t + lbp[0]);
                }
        }
    }
}

// ---- fused conv0 + conv1 persistent kernel, in-kernel x conversion ----
__global__ __launch_bounds__(256, 2) void fused_conv_k(
    const float* __restrict__ x,
    const float* __restrict__ b1, const float* __restrict__ g1, const float* __restrict__ be1,
    const float* __restrict__ b2, const float* __restrict__ g2, const float* __restrict__ be2,
    const float* __restrict__ lw, const float* __restrict__ lbp, float* __restrict__ pred)
{
    extern __shared__ char smem[];
    const uint32_t sb0 = smem_u32(smem);
    const uint32_t tiles = (sb0 + 127) & ~127u;
    char* smc = smem + (tiles - sb0);
    float* sPar = (float*)(smc + OFF_PAR);
    float* sSum = (float*)(smc + OFF_SUM);
    float* sSq  = (float*)(smc + OFF_SQ);
    float* sLin = (float*)(smc + OFF_LIN);
    const uint32_t mbF = tiles + OFF_MBAR;
    const int tid = threadIdx.x, lane = tid & 31, warp = tid >> 5;
    const int mw = warp >> 2, nw = warp & 3;
    const int bid = blockIdx.x;
    const int mBase = bid * 64;
    const bool fix0 = ((mBase & 511) == 0);
    const bool fix2 = (((mBase + 64) & 511) == 0);

    int base = 0;
    if (tid == 0) base = g_flag[bid];

    sPar[tid] = b1[tid];        sPar[256 + tid] = g1[tid];
    sPar[512 + tid] = be1[tid]; sPar[768 + tid] = 0.f;
    sPar[1024 + tid] = b2[tid]; sPar[1280 + tid] = g2[tid];
    sPar[1536 + tid] = be2[tid]; sPar[1792 + tid] = lw[tid];
    if (tid == 0) {
        MBAR_INIT(mbF, 1); MBAR_INIT(mbF + 8, 1);
        MBAR_INIT(mbF + 16, 8); MBAR_INIT(mbF + 24, 8);
    }
    __syncthreads();

    // issue W1 chunks 0,1 (overlaps x conversion below)
    if (tid == 224) {
        #pragma unroll
        for (int j = 0; j < 2; j++) {
            MBAR_EXPECT(mbF + 8 * j, W_TILE);
            bulk_cp(tiles + j * W_TILE, g_w1s + (size_t)j * W_TILE, W_TILE, mbF + 8 * j);
        }
    }

    // convert own x rows (with halo) fp32 -> fp16 swizzled into persistent A region
    for (int it = tid; it < 66 * 32; it += 256) {
        int row = it >> 5, s = it & 31;
        bool zero = (row == 0 && fix0) || (row == 65 && fix2);
        float4 v0 = make_float4(0.f, 0.f, 0.f, 0.f), v1 = v0;
        if (!zero) {
            const float4* src = reinterpret_cast<const float4*>(
                x + (size_t)(mBase - 1 + row) * 256 + s * 8);
            v0 = src[0]; v1 = src[1];
        }
        __half2 a = __floats2half2_rn(v0.x, v0.y), b = __floats2half2_rn(v0.z, v0.w);
        __half2 c = __floats2half2_rn(v1.x, v1.y), d = __floats2half2_rn(v1.z, v1.w);
        uint4 o = make_uint4(*(uint32_t*)&a, *(uint32_t*)&b, *(uint32_t*)&c, *(uint32_t*)&d);
        *reinterpret_cast<uint4*>(smc + OFF_A + row * 512 + (s >> 3) * 128
            + (((s & 7) ^ (row & 7)) << 4)) = o;
    }
    __syncthreads();

    int pha[2] = {0, 0}, eph[2] = {0, 0};

    // phase 0: x -> h1 (h1 written to smem A region + 2 halo rows to gmem)
    conv_phase<0>(smc, tiles, g_w1s, mBase, bid, tid, lane, mw, nw,
                  pha, eph, sPar, sSum, sSq, sLin, pred, lbp);

    // publish halo rows; wait only for needed neighbors; fill p=0 / p=65
    __threadfence();
    __syncthreads();
    if (tid == 0) {
        atomicExch(&g_flag[bid], base + 1);
        const int tgt = base + 1;
        if (!fix0) while (ld_acq(&g_flag[bid - 1]) != tgt) __nanosleep(32);
        if (!fix2) while (ld_acq(&g_flag[bid + 1]) != tgt) __nanosleep(32);
    }
    __syncthreads();
    if (warp == 0) {
        uint4 v = make_uint4(0, 0, 0, 0);
        if (!fix0) v = *reinterpret_cast<const uint4*>(g_h1halo + (bid - 1) * 1024 + 512 + lane * 16);
        *reinterpret_cast<uint4*>(smc + OFF_A + lane * 16) = v;
    } else if (warp == 1) {
        uint4 v = make_uint4(0, 0, 0, 0);
        if (!fix2) v = *reinterpret_cast<const uint4*>(g_h1halo + (bid + 1) * 1024 + lane * 16);
        *reinterpret_cast<uint4*>(smc + OFF_A + 65 * 512 + lane * 16) = v;
    }
    __syncthreads();

    // phase 1: h1 -> pred
    conv_phase<1>(smc, tiles, g_w2s, mBase, bid, tid, lane, mw, nw,
                  pha, eph, sPar + 1024, sSum, sSq, sLin, pred, lbp);
}

// ---- rowmap + gather (unchanged, proven) ----
__global__ __launch_bounds__(512) void rowmap_k(const float* __restrict__ target, int L) {
    int b = blockIdx.x, s = threadIdx.x;
    int lane = s & 31, wp = s >> 5;
    int d = (int)rintf(target[b * 512 + s]);
    int v = d;
    #pragma unroll
    for (int o = 1; o < 32; o <<= 1) {
        int t = __shfl_up_sync(0xffffffffu, v, o);
        if (lane >= o) v += t;
    }
    __shared__ int wsum[16];
    if (lane == 31) wsum[wp] = v;
    __syncthreads();
    if (s < 16) {
        int w = wsum[s];
        #pragma unroll
        for (int o = 1; o < 16; o <<= 1) {
            int t = __shfl_up_sync(0x0000ffffu, w, o);
            if (s >= o) w += t;
        }
        wsum[s] = w;
    }
    __syncthreads();
    int end = v + (wp ? wsum[wp - 1] : 0);
    int start = end - d;
    int* rm = g_rowmap + (size_t)b * L;
    for (int l = s; l < L; l += 512) rm[l] = -1;
    __syncthreads();
    if (start < L) {
        int e = min(end, L);
        for (int l = start; l < e; ++l) rm[l] = s;
    }
}

__global__ __launch_bounds__(256) void gather_k(const float* __restrict__ x,
                                                float* __restrict__ out, int L) {
    int rowId = blockIdx.x * 4 + (threadIdx.x >> 6);
    if (rowId >= B_ * L) return;
    int t = threadIdx.x & 63;
    int b = rowId / L;
    int s = g_rowmap[rowId];
    float4 v = make_float4(0.f, 0.f, 0.f, 0.f);
    if (s >= 0)
        v = *reinterpret_cast<const float4*>(x + (size_t)((b << 9) + s) * D_ + (t << 2));
    *reinterpret_cast<float4*>(out + (size_t)rowId * D_ + (t << 2)) = v;
}

extern "C" void kernel_launch(void* const* d_in, const int* in_sizes, int n_in,
                              void* d_out, int out_size) {
    const float* x   = (const float*)d_in[0];
    const float* tgt = (const float*)d_in[1];
    const float* c1w = (const float*)d_in[2];
    const float* c1b = (const float*)d_in[3];
    const float* c2w = (const float*)d_in[4];
    const float* c2b = (const float*)d_in[5];
    const float* n1g = (const float*)d_in[6];
    const float* n1b = (const float*)d_in[7];
    const float* n2g = (const float*)d_in[8];
    const float* n2b = (const float*)d_in[9];
    const float* lw  = (const float*)d_in[10];
    const float* lb  = (const float*)d_in[11];

    float* out = (float*)d_out;
    int L = (out_size - B_ * S_) / (B_ * D_);
    float* pred = out + (size_t)B_ * L * D_;

    static cudaStream_t sHi = nullptr, sLo = nullptr;
    static cudaEvent_t evF = nullptr, evW = nullptr, evH = nullptr, evJ = nullptr;
    if (sHi == nullptr) {
        int pLo, pHi;
        cudaDeviceGetStreamPriorityRange(&pLo, &pHi);
        cudaStreamCreateWithPriority(&sHi, cudaStreamNonBlocking, pHi);
        cudaStreamCreateWithPriority(&sLo, cudaStreamNonBlocking, pLo);
        cudaEventCreateWithFlags(&evF, cudaEventDisableTiming);
        cudaEventCreateWithFlags(&evW, cudaEventDisableTiming);
        cudaEventCreateWithFlags(&evH, cudaEventDisableTiming);
        cudaEventCreateWithFlags(&evJ, cudaEventDisableTiming);
        cudaFuncSetAttribute(fused_conv_k, cudaFuncAttributeMaxDynamicSharedMemorySize, SMEM_TOTAL);
    }

    // fork
    cudaEventRecord(evF, 0);
    cudaStreamWaitEvent(sHi, evF, 0);
    cudaStreamWaitEvent(sLo, evF, 0);

    // low-priority branch: weight prep + length regulator
    cvt_w_k<<<2 * F_ * KK_ / 256, 256, 0, sLo>>>(c1w, c2w);
    cudaEventRecord(evW, sLo);
    rowmap_k<<<B_, 512, 0, sLo>>>(tgt, L);
    gather_k<<<(B_ * L + 3) / 4, 256, 0, sLo>>>(x, out, L);
    cudaEventRecord(evJ, sLo);

    // high-priority branch: fused duration predictor
    cudaStreamWaitEvent(sHi, evW, 0);
    fused_conv_k<<<256, 256, SMEM_TOTAL, sHi>>>(x, c1b, n1g, n1b, c2b, n2g, n2b, lw, lb, pred);
    cudaEventRecord(evH, sHi);

    // join
    cudaStreamWaitEvent(0, evH, 0);
    cudaStreamWaitEvent(0, evJ, 0);
}

// round 15
// speedup vs baseline: 1.7792x; 1.3803x over previous
#include <cuda_runtime.h>
#include <cuda_fp16.h>
#include <cstdint>

#define B_  32
#define S_  512
#define D_  256
#define F_  256
#define BS_ 16384
#define KK_ 768
#define NCH 12
#define W_TILE 32768               // 256 rows x 128B, pre-swizzled
#define OFF_A   (2*W_TILE)         // 65536: persistent A region, 66 rows x 512B
#define OFF_PAR (OFF_A + 66*512)   // 99328
#define OFF_SUM (OFF_PAR + 8192)   // 107520
#define OFF_SQ  (OFF_SUM + 1024)
#define OFF_LIN (OFF_SQ  + 1024)
#define OFF_MBAR (OFF_LIN + 1024)  // 110592
#define SMEM_TOTAL (OFF_MBAR + 64 + 128)   // 110784 -> 2 CTAs/SM

__device__ char g_w1s[NCH*W_TILE];
__device__ char g_w2s[NCH*W_TILE];
__device__ char g_h1halo[256*1024];        // [bid][2][512B] swizzled rows
__device__ int  g_rowmap[B_*4608];
__device__ int  g_flag[256];               // monotonic per-launch counters

__device__ __forceinline__ uint32_t smem_u32(const void* p) {
    uint32_t a;
    asm("{ .reg .u64 t; cvta.to.shared.u64 t, %1; cvt.u32.u64 %0, t; }" : "=r"(a) : "l"(p));
    return a;
}
#define MBAR_INIT(a, c) asm volatile("mbarrier.init.shared.b64 [%0], %1;" :: "r"((uint32_t)(a)), "r"((uint32_t)(c)) : "memory")
#define MBAR_EXPECT(a, b) asm volatile("mbarrier.arrive.expect_tx.shared.b64 _, [%0], %1;" :: "r"((uint32_t)(a)), "r"((uint32_t)(b)) : "memory")
#define MBAR_ARRIVE(a) asm volatile("mbarrier.arrive.shared.b64 _, [%0];" :: "r"((uint32_t)(a)) : "memory")
#define MBAR_WAIT(a, ph) do { \
    uint32_t _m = (uint32_t)(a), _p = (uint32_t)(ph), _d; \
    asm volatile("{ .reg .pred p; mbarrier.try_wait.parity.acquire.cta.shared::cta.b64 p, [%1], %2; selp.b32 %0, 1, 0, p; }" \
        : "=r"(_d) : "r"(_m), "r"(_p) : "memory"); \
    if (!_d) { asm volatile("{ .reg .pred P1;\nWL_%=:\n" \
        "mbarrier.try_wait.parity.acquire.cta.shared::cta.b64 P1, [%0], %1, 0x989680;\n" \
        "@P1 bra.uni WD_%=;\nbra.uni WL_%=;\nWD_%=:\n}" :: "r"(_m), "r"(_p) : "memory"); } \
} while (0)
__device__ __forceinline__ void bulk_cp(uint32_t dst, const void* src, uint32_t bytes, uint32_t mbar) {
    asm volatile("cp.async.bulk.shared::cta.global.mbarrier::complete_tx::bytes [%0], [%1], %2, [%3];"
        :: "r"(dst), "l"(src), "r"(bytes), "r"(mbar) : "memory");
}
__device__ __forceinline__ void ldsm_x4(uint32_t* r, uint32_t a) {
    asm volatile("ldmatrix.sync.aligned.m8n8.x4.shared.b16 {%0,%1,%2,%3}, [%4];"
        : "=r"(r[0]), "=r"(r[1]), "=r"(r[2]), "=r"(r[3]) : "r"(a));
}
__device__ __forceinline__ void mma_f16(float* d, const uint32_t* a, const uint32_t* b) {
    asm volatile("mma.sync.aligned.m16n8k16.row.col.f32.f16.f16.f32 "
        "{%0,%1,%2,%3}, {%4,%5,%6,%7}, {%8,%9}, {%0,%1,%2,%3};"
        : "+f"(d[0]), "+f"(d[1]), "+f"(d[2]), "+f"(d[3])
        : "r"(a[0]), "r"(a[1]), "r"(a[2]), "r"(a[3]), "r"(b[0]), "r"(b[1]));
}
__device__ __forceinline__ int ld_acq(const int* p) {
    int v; asm volatile("ld.acquire.gpu.global.s32 %0, [%1];" : "=r"(v) : "l"(p)); return v;
}

// ---- prep: weights -> chunked+swizzled (split: W1 and W2 as separate kernels) ----
template<int PH>
__global__ __launch_bounds__(256) void cvt_w_k(const float* __restrict__ w) {
    int idx = blockIdx.x * 256 + threadIdx.x;
    int f = idx / 768, rem = idx - f * 768;
    int tap = rem >> 8, c = rem & 255;
    int kk = tap * 256 + c;
    int chunk = kk >> 6, kc = kk & 63;
    __half hv = __float2half(w[f * 768 + c * 3 + tap]);
    uint32_t byte = (uint32_t)(2 * kc) ^ (uint32_t)((f & 7) << 4);
    *reinterpret_cast<__half*>((PH ? g_w2s : g_w1s)
        + (size_t)chunk * W_TILE + (size_t)f * 128 + byte) = hv;
}

// ---- one conv phase main loop + epilogue (producer = tid 0, the laggard warp) ----
template<int PH>
__device__ __forceinline__ void conv_phase(
    char* smc, uint32_t tiles, const char* Wst,
    int mBase, int bid, int tid, int lane, int mw, int nw,
    int* pha, int* eph, const float* par,
    float* sSum, float* sSq, float* sLin,
    float* pred, const float* lbp)
{
    const uint32_t mbF = tiles + OFF_MBAR, mbE = mbF + 16;
    const uint32_t aA = tiles + OFF_A;

    float acc[2][8][4];
    #pragma unroll
    for (int a = 0; a < 2; a++)
        #pragma unroll
        for (int b = 0; b < 8; b++)
            #pragma unroll
            for (int c = 0; c < 4; c++) acc[a][b][c] = 0.f;

    for (int i = 0; i < NCH; i++) {
        const int st = i & 1;
        const int tap = i >> 2;
        const int cg = i & 3;
        if (tid == 0 && i >= 1 && i + 1 < NCH) {
            const int st2 = st ^ 1;
            MBAR_WAIT(mbE + 8 * st2, eph[st2]); eph[st2] ^= 1;
            MBAR_EXPECT(mbF + 8 * st2, W_TILE);
            bulk_cp(tiles + st2 * W_TILE, Wst + (size_t)(i + 1) * W_TILE, W_TILE, mbF + 8 * st2);
        }
        MBAR_WAIT(mbF + 8 * st, pha[st]); pha[st] ^= 1;
        const uint32_t wT = tiles + st * W_TILE;

        #pragma unroll
        for (int ks = 0; ks < 4; ks++) {
            uint32_t bf[8][2];
            #pragma unroll
            for (int njp = 0; njp < 4; njp++) {
                int f = nw * 64 + (2 * njp + ((lane >> 4) & 1)) * 8 + (lane & 7);
                int kseg = ks * 2 + ((lane >> 3) & 1);
                uint32_t ad = wT + (uint32_t)f * 128 + (uint32_t)((kseg ^ (f & 7)) << 4);
                uint32_t r[4];
                ldsm_x4(r, ad);
                bf[2 * njp][0] = r[0]; bf[2 * njp][1] = r[1];
                bf[2 * njp + 1][0] = r[2]; bf[2 * njp + 1][1] = r[3];
            }
            #pragma unroll
            for (int mi = 0; mi < 2; mi++) {
                int p = mw * 32 + mi * 16 + (lane & 7) + ((lane >> 3) & 1) * 8 + tap;
                int kseg = ks * 2 + ((lane >> 4) & 1);
                uint32_t ad = aA + (uint32_t)p * 512 + (uint32_t)cg * 128
                              + (uint32_t)((kseg ^ (p & 7)) << 4);
                uint32_t af[4];
                ldsm_x4(af, ad);
                #pragma unroll
                for (int nj = 0; nj < 8; nj++)
                    mma_f16(acc[mi][nj], af, bf[nj]);
            }
        }
        if (lane == 0) MBAR_ARRIVE(mbE + 8 * st);
    }
    __syncthreads();

    // ---- PH=0 hook: drain leftover empties, prefetch W2 chunks 0/1 ----
    if (PH == 0 && tid == 0) {
        MBAR_WAIT(mbE, eph[0]); eph[0] ^= 1;
        MBAR_WAIT(mbE + 8, eph[1]); eph[1] ^= 1;
        #pragma unroll
        for (int j = 0; j < 2; j++) {
            MBAR_EXPECT(mbF + 8 * j, W_TILE);
            bulk_cp(tiles + j * W_TILE, g_w2s + (size_t)j * W_TILE, W_TILE, mbF + 8 * j);
        }
    }

    // ---- epilogue: bias + LN ----
    #pragma unroll
    for (int mi = 0; mi < 2; mi++)
        #pragma unroll
        for (int rh = 0; rh < 2; rh++) {
            float s = 0.f, q = 0.f;
            #pragma unroll
            for (int nj = 0; nj < 8; nj++)
                #pragma unroll
                for (int h = 0; h < 2; h++) {
                    int col = nw * 64 + nj * 8 + 2 * (lane & 3) + h;
                    float v = acc[mi][nj][rh * 2 + h] + par[col];
                    acc[mi][nj][rh * 2 + h] = v;
                    s += v; q = fmaf(v, v, q);
                }
            s += __shfl_xor_sync(0xffffffffu, s, 1); s += __shfl_xor_sync(0xffffffffu, s, 2);
            q += __shfl_xor_sync(0xffffffffu, q, 1); q += __shfl_xor_sync(0xffffffffu, q, 2);
            if ((lane & 3) == 0) {
                int r = mw * 32 + mi * 16 + rh * 8 + (lane >> 2);
                sSum[nw * 64 + r] = s; sSq[nw * 64 + r] = q;
            }
        }
    __syncthreads();

    float lacc[2][2];
    #pragma unroll
    for (int mi = 0; mi < 2; mi++)
        #pragma unroll
        for (int rh = 0; rh < 2; rh++) {
            int r = mw * 32 + mi * 16 + rh * 8 + (lane >> 2);
            float tot = sSum[r] + sSum[64 + r] + sSum[128 + r] + sSum[192 + r];
            float tq  = sSq[r]  + sSq[64 + r]  + sSq[128 + r]  + sSq[192 + r];
            float mu = tot * (1.f / 256.f);
            float rstd = rsqrtf(tq * (1.f / 256.f) - mu * mu + 1e-5f);
            const int p = r + 1;
            float la = 0.f;
            #pragma unroll
            for (int nj = 0; nj < 8; nj++) {
                int col0 = nw * 64 + nj * 8 + 2 * (lane & 3);
                float v0 = acc[mi][nj][rh * 2 + 0], v1 = acc[mi][nj][rh * 2 + 1];
                float o0 = fmaxf(0.f, fmaf((v0 - mu) * rstd, par[256 + col0],     par[512 + col0]));
                float o1 = fmaxf(0.f, fmaf((v1 - mu) * rstd, par[256 + col0 + 1], par[512 + col0 + 1]));
                if (PH == 0) {
                    __half2 hxv = __floats2half2_rn(o0, o1);
                    uint32_t hx = *reinterpret_cast<uint32_t*>(&hxv);
                    uint32_t off = (uint32_t)(col0 >> 6) * 128
                                 + (uint32_t)((((col0 >> 3) & 7) ^ (p & 7)) << 4)
                                 + (uint32_t)((col0 & 7) * 2);
                    *reinterpret_cast<uint32_t*>(smc + OFF_A + p * 512 + off) = hx;
                    if (r == 0)
                        *reinterpret_cast<uint32_t*>(g_h1halo + bid * 1024 + off) = hx;
                    if (r == 63)
                        *reinterpret_cast<uint32_t*>(g_h1halo + bid * 1024 + 512 + off) = hx;
                } else {
                    la = fmaf(o0, par[768 + col0], la);
                    la = fmaf(o1, par[768 + col0 + 1], la);
                }
            }
            lacc[mi][rh] = la;
        }

    if (PH == 1) {
        #pragma unroll
        for (int mi = 0; mi < 2; mi++)
            #pragma unroll
            for (int rh = 0; rh < 2; rh++) {
                float la = lacc[mi][rh];
                la += __shfl_xor_sync(0xffffffffu, la, 1);
                la += __shfl_xor_sync(0xffffffffu, la, 2);
                if ((lane & 3) == 0)
                    sLin[nw * 64 + mw * 32 + mi * 16 + rh * 8 + (lane >> 2)] = la;
            }
        __syncthreads();
        if (nw == 0 && (lane & 3) == 0) {
            #pragma unroll
            for (int mi = 0; mi < 2; mi++)
                #pragma unroll
                for (int rh = 0; rh < 2; rh++) {
                    int r = mw * 32 + mi * 16 + rh * 8 + (lane >> 2);
                    float t = sLin[r] + sLin[64 + r] + sLin[128 + r] + sLin[192 + r];
                    pred[mBase + r] = fmaxf(0.f, t + lbp[0]);
                }
        }
    }
}

// ---- fused conv0 + conv1 persistent kernel, in-kernel x conversion ----
__global__ __launch_bounds__(256, 2) void fused_conv_k(
    const float* __restrict__ x,
    const float* __restrict__ b1, const float* __restrict__ g1, const float* __restrict__ be1,
    const float* __restrict__ b2, const float* __restrict__ g2, const float* __restrict__ be2,
    const float* __restrict__ lw, const float* __restrict__ lbp, float* __restrict__ pred)
{
    extern __shared__ char smem[];
    const uint32_t sb0 = smem_u32(smem);
    const uint32_t tiles = (sb0 + 127) & ~127u;
    char* smc = smem + (tiles - sb0);
    float* sPar = (float*)(smc + OFF_PAR);
    float* sSum = (float*)(smc + OFF_SUM);
    float* sSq  = (float*)(smc + OFF_SQ);
    float* sLin = (float*)(smc + OFF_LIN);
    const uint32_t mbF = tiles + OFF_MBAR;
    const int tid = threadIdx.x, lane = tid & 31, warp = tid >> 5;
    const int mw = warp >> 2, nw = warp & 3;
    const int bid = blockIdx.x;
    const int mBase = bid * 64;
    const bool fix0 = ((mBase & 511) == 0);
    const bool fix2 = (((mBase + 64) & 511) == 0);

    int base = 0;
    if (tid == 0) base = g_flag[bid];

    sPar[tid] = b1[tid];        sPar[256 + tid] = g1[tid];
    sPar[512 + tid] = be1[tid]; sPar[768 + tid] = 0.f;
    sPar[1024 + tid] = b2[tid]; sPar[1280 + tid] = g2[tid];
    sPar[1536 + tid] = be2[tid]; sPar[1792 + tid] = lw[tid];
    if (tid == 0) {
        MBAR_INIT(mbF, 1); MBAR_INIT(mbF + 8, 1);
        MBAR_INIT(mbF + 16, 8); MBAR_INIT(mbF + 24, 8);
    }
    __syncthreads();

    // issue W1 chunks 0,1 (overlaps x conversion below)
    if (tid == 0) {
        #pragma unroll
        for (int j = 0; j < 2; j++) {
            MBAR_EXPECT(mbF + 8 * j, W_TILE);
            bulk_cp(tiles + j * W_TILE, g_w1s + (size_t)j * W_TILE, W_TILE, mbF + 8 * j);
        }
    }

    // convert own x rows (with halo) fp32 -> fp16 swizzled into persistent A region
    for (int it = tid; it < 66 * 32; it += 256) {
        int row = it >> 5, s = it & 31;
        bool zero = (row == 0 && fix0) || (row == 65 && fix2);
        float4 v0 = make_float4(0.f, 0.f, 0.f, 0.f), v1 = v0;
        if (!zero) {
            const float4* src = reinterpret_cast<const float4*>(
                x + (size_t)(mBase - 1 + row) * 256 + s * 8);
            v0 = src[0]; v1 = src[1];
        }
        __half2 a = __floats2half2_rn(v0.x, v0.y), b = __floats2half2_rn(v0.z, v0.w);
        __half2 c = __floats2half2_rn(v1.x, v1.y), d = __floats2half2_rn(v1.z, v1.w);
        uint4 o = make_uint4(*(uint32_t*)&a, *(uint32_t*)&b, *(uint32_t*)&c, *(uint32_t*)&d);
        *reinterpret_cast<uint4*>(smc + OFF_A + row * 512 + (s >> 3) * 128
            + (((s & 7) ^ (row & 7)) << 4)) = o;
    }
    __syncthreads();

    int pha[2] = {0, 0}, eph[2] = {0, 0};

    // phase 0: x -> h1 (h1 written to smem A region + 2 halo rows to gmem)
    conv_phase<0>(smc, tiles, g_w1s, mBase, bid, tid, lane, mw, nw,
                  pha, eph, sPar, sSum, sSq, sLin, pred, lbp);

    // publish halo rows; wait only for needed neighbors; fill p=0 / p=65
    __threadfence();
    __syncthreads();
    if (tid == 0) {
        atomicExch(&g_flag[bid], base + 1);
        const int tgt = base + 1;
        if (!fix0) while (ld_acq(&g_flag[bid - 1]) != tgt) __nanosleep(32);
        if (!fix2) while (ld_acq(&g_flag[bid + 1]) != tgt) __nanosleep(32);
    }
    __syncthreads();
    if (warp == 0) {
        uint4 v = make_uint4(0, 0, 0, 0);
        if (!fix0) v = *reinterpret_cast<const uint4*>(g_h1halo + (bid - 1) * 1024 + 512 + lane * 16);
        *reinterpret_cast<uint4*>(smc + OFF_A + lane * 16) = v;
    } else if (warp == 1) {
        uint4 v = make_uint4(0, 0, 0, 0);
        if (!fix2) v = *reinterpret_cast<const uint4*>(g_h1halo + (bid + 1) * 1024 + lane * 16);
        *reinterpret_cast<uint4*>(smc + OFF_A + 65 * 512 + lane * 16) = v;
    }
    __syncthreads();

    // phase 1: h1 -> pred
    conv_phase<1>(smc, tiles, g_w2s, mBase, bid, tid, lane, mw, nw,
                  pha, eph, sPar + 1024, sSum, sSq, sLin, pred, lbp);
}

// ---- rowmap + gather (unchanged, proven) ----
__global__ __launch_bounds__(512) void rowmap_k(const float* __restrict__ target, int L) {
    int b = blockIdx.x, s = threadIdx.x;
    int lane = s & 31, wp = s >> 5;
    int d = (int)rintf(target[b * 512 + s]);
    int v = d;
    #pragma unroll
    for (int o = 1; o < 32; o <<= 1) {
        int t = __shfl_up_sync(0xffffffffu, v, o);
        if (lane >= o) v += t;
    }
    __shared__ int wsum[16];
    if (lane == 31) wsum[wp] = v;
    __syncthreads();
    if (s < 16) {
        int w = wsum[s];
        #pragma unroll
        for (int o = 1; o < 16; o <<= 1) {
            int t = __shfl_up_sync(0x0000ffffu, w, o);
            if (s >= o) w += t;
        }
        wsum[s] = w;
    }
    __syncthreads();
    int end = v + (wp ? wsum[wp - 1] : 0);
    int start = end - d;
    int* rm = g_rowmap + (size_t)b * L;
    for (int l = s; l < L; l += 512) rm[l] = -1;
    __syncthreads();
    if (start < L) {
        int e = min(end, L);
        for (int l = start; l < e; ++l) rm[l] = s;
    }
}

__global__ __launch_bounds__(256) void gather_k(const float* __restrict__ x,
                                                float* __restrict__ out, int L) {
    int rowId = blockIdx.x * 4 + (threadIdx.x >> 6);
    if (rowId >= B_ * L) return;
    int t = threadIdx.x & 63;
    int b = rowId / L;
    int s = g_rowmap[rowId];
    float4 v = make_float4(0.f, 0.f, 0.f, 0.f);
    if (s >= 0)
        v = *reinterpret_cast<const float4*>(x + (size_t)((b << 9) + s) * D_ + (t << 2));
    *reinterpret_cast<float4*>(out + (size_t)rowId * D_ + (t << 2)) = v;
}

extern "C" void kernel_launch(void* const* d_in, const int* in_sizes, int n_in,
                              void* d_out, int out_size) {
    const float* x   = (const float*)d_in[0];
    const float* tgt = (const float*)d_in[1];
    const float* c1w = (const float*)d_in[2];
    const float* c1b = (const float*)d_in[3];
    const float* c2w = (const float*)d_in[4];
    const float* c2b = (const float*)d_in[5];
    const float* n1g = (const float*)d_in[6];
    const float* n1b = (const float*)d_in[7];
    const float* n2g = (const float*)d_in[8];
    const float* n2b = (const float*)d_in[9];
    const float* lw  = (const float*)d_in[10];
    const float* lb  = (const float*)d_in[11];

    float* out = (float*)d_out;
    int L = (out_size - B_ * S_) / (B_ * D_);
    float* pred = out + (size_t)B_ * L * D_;

    static cudaStream_t sHi = nullptr, sLo = nullptr;
    static cudaEvent_t evF = nullptr, evW = nullptr, evH = nullptr, evJ = nullptr;
    if (sHi == nullptr) {
        int pLo, pHi;
        cudaDeviceGetStreamPriorityRange(&pLo, &pHi);
        cudaStreamCreateWithPriority(&sHi, cudaStreamNonBlocking, pHi);
        cudaStreamCreateWithPriority(&sLo, cudaStreamNonBlocking, pLo);
        cudaEventCreateWithFlags(&evF, cudaEventDisableTiming);
        cudaEventCreateWithFlags(&evW, cudaEventDisableTiming);
        cudaEventCreateWithFlags(&evH, cudaEventDisableTiming);
        cudaEventCreateWithFlags(&evJ, cudaEventDisableTiming);
        cudaFuncSetAttribute(fused_conv_k, cudaFuncAttributeMaxDynamicSharedMemorySize, SMEM_TOTAL);
    }

    // fork
    cudaEventRecord(evF, 0);
    cudaStreamWaitEvent(sHi, evF, 0);
    cudaStreamWaitEvent(sLo, evF, 0);

    // low-priority branch: W1 prep (gates conv), then W2 prep + length regulator
    cvt_w_k<0><<<F_ * KK_ / 256, 256, 0, sLo>>>(c1w);
    cudaEventRecord(evW, sLo);
    cvt_w_k<1><<<F_ * KK_ / 256, 256, 0, sLo>>>(c2w);
    rowmap_k<<<B_, 512, 0, sLo>>>(tgt, L);
    gather_k<<<(B_ * L + 3) / 4, 256, 0, sLo>>>(x, out, L);
    cudaEventRecord(evJ, sLo);

    // high-priority branch: fused duration predictor (needs only W1 to start)
    cudaStreamWaitEvent(sHi, evW, 0);
    fused_conv_k<<<256, 256, SMEM_TOTAL, sHi>>>(x, c1b, n1g, n1b, c2b, n2g, n2b, lw, lb, pred);
    cudaEventRecord(evH, sHi);

    // join
    cudaStreamWaitEvent(0, evH, 0);
    cudaStreamWaitEvent(0, evJ, 0);
}

// round 16
// speedup vs baseline: 1.8235x; 1.0249x over previous
#include <cuda_runtime.h>
#include <cuda_fp16.h>
#include <cstdint>

#define B_  32
#define S_  512
#define D_  256
#define F_  256
#define BS_ 16384
#define KK_ 768
#define NCH 12
#define W_TILE 32768               // 256 rows x 128B, pre-swizzled
#define OFF_A   (2*W_TILE)         // 65536: persistent A region, 66 rows x 512B
#define OFF_PAR (OFF_A + 66*512)   // 99328
#define OFF_SUM (OFF_PAR + 8192)   // 107520
#define OFF_SQ  (OFF_SUM + 1024)
#define OFF_LIN (OFF_SQ  + 1024)
#define OFF_MBAR (OFF_LIN + 1024)  // 110592
#define SMEM_TOTAL (OFF_MBAR + 64 + 128)   // 110784 -> 2 CTAs/SM

__device__ char g_w1s[NCH*W_TILE];
__device__ char g_w2s[NCH*W_TILE];
__device__ char g_h1halo[256*1024];        // [bid][2][512B] swizzled rows
__device__ int  g_rowmap[B_*4608];
__device__ int  g_flag[256];               // monotonic per-launch counters

__device__ __forceinline__ uint32_t smem_u32(const void* p) {
    uint32_t a;
    asm("{ .reg .u64 t; cvta.to.shared.u64 t, %1; cvt.u32.u64 %0, t; }" : "=r"(a) : "l"(p));
    return a;
}
#define MBAR_INIT(a, c) asm volatile("mbarrier.init.shared.b64 [%0], %1;" :: "r"((uint32_t)(a)), "r"((uint32_t)(c)) : "memory")
#define MBAR_EXPECT(a, b) asm volatile("mbarrier.arrive.expect_tx.shared.b64 _, [%0], %1;" :: "r"((uint32_t)(a)), "r"((uint32_t)(b)) : "memory")
#define MBAR_ARRIVE(a) asm volatile("mbarrier.arrive.shared.b64 _, [%0];" :: "r"((uint32_t)(a)) : "memory")
#define MBAR_WAIT(a, ph) do { \
    uint32_t _m = (uint32_t)(a), _p = (uint32_t)(ph), _d; \
    asm volatile("{ .reg .pred p; mbarrier.try_wait.parity.acquire.cta.shared::cta.b64 p, [%1], %2; selp.b32 %0, 1, 0, p; }" \
        : "=r"(_d) : "r"(_m), "r"(_p) : "memory"); \
    if (!_d) { asm volatile("{ .reg .pred P1;\nWL_%=:\n" \
        "mbarrier.try_wait.parity.acquire.cta.shared::cta.b64 P1, [%0], %1, 0x989680;\n" \
        "@P1 bra.uni WD_%=;\nbra.uni WL_%=;\nWD_%=:\n}" :: "r"(_m), "r"(_p) : "memory"); } \
} while (0)
__device__ __forceinline__ void bulk_cp(uint32_t dst, const void* src, uint32_t bytes, uint32_t mbar) {
    asm volatile("cp.async.bulk.shared::cta.global.mbarrier::complete_tx::bytes [%0], [%1], %2, [%3];"
        :: "r"(dst), "l"(src), "r"(bytes), "r"(mbar) : "memory");
}
__device__ __forceinline__ void ldsm_x4(uint32_t* r, uint32_t a) {
    asm volatile("ldmatrix.sync.aligned.m8n8.x4.shared.b16 {%0,%1,%2,%3}, [%4];"
        : "=r"(r[0]), "=r"(r[1]), "=r"(r[2]), "=r"(r[3]) : "r"(a));
}
__device__ __forceinline__ void mma_f16(float* d, const uint32_t* a, const uint32_t* b) {
    asm volatile("mma.sync.aligned.m16n8k16.row.col.f32.f16.f16.f32 "
        "{%0,%1,%2,%3}, {%4,%5,%6,%7}, {%8,%9}, {%0,%1,%2,%3};"
        : "+f"(d[0]), "+f"(d[1]), "+f"(d[2]), "+f"(d[3])
        : "r"(a[0]), "r"(a[1]), "r"(a[2]), "r"(a[3]), "r"(b[0]), "r"(b[1]));
}
__device__ __forceinline__ int ld_acq(const int* p) {
    int v; asm volatile("ld.acquire.gpu.global.s32 %0, [%1];" : "=r"(v) : "l"(p)); return v;
}

// ---- prep: weights -> chunked+swizzled (combined, as in R12) ----
__global__ __launch_bounds__(256) void cvt_w_k(const float* __restrict__ w1,
                                               const float* __restrict__ w2) {
    int gid = blockIdx.x * 256 + threadIdx.x;
    int ph = gid >= F_ * KK_;
    int idx = ph ? gid - F_ * KK_ : gid;
    int f = idx / 768, rem = idx - f * 768;
    int tap = rem >> 8, c = rem & 255;
    int kk = tap * 256 + c;
    int chunk = kk >> 6, kc = kk & 63;
    const float* w = ph ? w2 : w1;
    __half hv = __float2half(w[f * 768 + c * 3 + tap]);
    uint32_t byte = (uint32_t)(2 * kc) ^ (uint32_t)((f & 7) << 4);
    *reinterpret_cast<__half*>((ph ? g_w2s : g_w1s)
        + (size_t)chunk * W_TILE + (size_t)f * 128 + byte) = hv;
}

// ---- one conv phase main loop + epilogue (producer = tid 0, the laggard warp) ----
template<int PH>
__device__ __forceinline__ void conv_phase(
    char* smc, uint32_t tiles, const char* Wst,
    int mBase, int bid, int tid, int lane, int mw, int nw,
    int* pha, int* eph, const float* par,
    float* sSum, float* sSq, float* sLin,
    float* pred, const float* lbp)
{
    const uint32_t mbF = tiles + OFF_MBAR, mbE = mbF + 16;
    const uint32_t aA = tiles + OFF_A;

    float acc[2][8][4];
    #pragma unroll
    for (int a = 0; a < 2; a++)
        #pragma unroll
        for (int b = 0; b < 8; b++)
            #pragma unroll
            for (int c = 0; c < 4; c++) acc[a][b][c] = 0.f;

    for (int i = 0; i < NCH; i++) {
        const int st = i & 1;
        const int tap = i >> 2;
        const int cg = i & 3;
        if (tid == 0 && i >= 1 && i + 1 < NCH) {
            const int st2 = st ^ 1;
            MBAR_WAIT(mbE + 8 * st2, eph[st2]); eph[st2] ^= 1;
            MBAR_EXPECT(mbF + 8 * st2, W_TILE);
            bulk_cp(tiles + st2 * W_TILE, Wst + (size_t)(i + 1) * W_TILE, W_TILE, mbF + 8 * st2);
        }
        MBAR_WAIT(mbF + 8 * st, pha[st]); pha[st] ^= 1;
        const uint32_t wT = tiles + st * W_TILE;

        #pragma unroll
        for (int ks = 0; ks < 4; ks++) {
            uint32_t bf[8][2];
            #pragma unroll
            for (int njp = 0; njp < 4; njp++) {
                int f = nw * 64 + (2 * njp + ((lane >> 4) & 1)) * 8 + (lane & 7);
                int kseg = ks * 2 + ((lane >> 3) & 1);
                uint32_t ad = wT + (uint32_t)f * 128 + (uint32_t)((kseg ^ (f & 7)) << 4);
                uint32_t r[4];
                ldsm_x4(r, ad);
                bf[2 * njp][0] = r[0]; bf[2 * njp][1] = r[1];
                bf[2 * njp + 1][0] = r[2]; bf[2 * njp + 1][1] = r[3];
            }
            #pragma unroll
            for (int mi = 0; mi < 2; mi++) {
                int p = mw * 32 + mi * 16 + (lane & 7) + ((lane >> 3) & 1) * 8 + tap;
                int kseg = ks * 2 + ((lane >> 4) & 1);
                uint32_t ad = aA + (uint32_t)p * 512 + (uint32_t)cg * 128
                              + (uint32_t)((kseg ^ (p & 7)) << 4);
                uint32_t af[4];
                ldsm_x4(af, ad);
                #pragma unroll
                for (int nj = 0; nj < 8; nj++)
                    mma_f16(acc[mi][nj], af, bf[nj]);
            }
        }
        if (lane == 0) MBAR_ARRIVE(mbE + 8 * st);
    }
    __syncthreads();

    // ---- PH=0 hook: drain leftover empties, prefetch W2 chunks 0/1 ----
    if (PH == 0 && tid == 0) {
        MBAR_WAIT(mbE, eph[0]); eph[0] ^= 1;
        MBAR_WAIT(mbE + 8, eph[1]); eph[1] ^= 1;
        #pragma unroll
        for (int j = 0; j < 2; j++) {
            MBAR_EXPECT(mbF + 8 * j, W_TILE);
            bulk_cp(tiles + j * W_TILE, g_w2s + (size_t)j * W_TILE, W_TILE, mbF + 8 * j);
        }
    }

    // ---- epilogue: bias + LN ----
    #pragma unroll
    for (int mi = 0; mi < 2; mi++)
        #pragma unroll
        for (int rh = 0; rh < 2; rh++) {
            float s = 0.f, q = 0.f;
            #pragma unroll
            for (int nj = 0; nj < 8; nj++)
                #pragma unroll
                for (int h = 0; h < 2; h++) {
                    int col = nw * 64 + nj * 8 + 2 * (lane & 3) + h;
                    float v = acc[mi][nj][rh * 2 + h] + par[col];
                    acc[mi][nj][rh * 2 + h] = v;
                    s += v; q = fmaf(v, v, q);
                }
            s += __shfl_xor_sync(0xffffffffu, s, 1); s += __shfl_xor_sync(0xffffffffu, s, 2);
            q += __shfl_xor_sync(0xffffffffu, q, 1); q += __shfl_xor_sync(0xffffffffu, q, 2);
            if ((lane & 3) == 0) {
                int r = mw * 32 + mi * 16 + rh * 8 + (lane >> 2);
                sSum[nw * 64 + r] = s; sSq[nw * 64 + r] = q;
            }
        }
    __syncthreads();

    float lacc[2][2];
    #pragma unroll
    for (int mi = 0; mi < 2; mi++)
        #pragma unroll
        for (int rh = 0; rh < 2; rh++) {
            int r = mw * 32 + mi * 16 + rh * 8 + (lane >> 2);
            float tot = sSum[r] + sSum[64 + r] + sSum[128 + r] + sSum[192 + r];
            float tq  = sSq[r]  + sSq[64 + r]  + sSq[128 + r]  + sSq[192 + r];
            float mu = tot * (1.f / 256.f);
            float rstd = rsqrtf(tq * (1.f / 256.f) - mu * mu + 1e-5f);
            const int p = r + 1;
            float la = 0.f;
            #pragma unroll
            for (int nj = 0; nj < 8; nj++) {
                int col0 = nw * 64 + nj * 8 + 2 * (lane & 3);
                float v0 = acc[mi][nj][rh * 2 + 0], v1 = acc[mi][nj][rh * 2 + 1];
                float o0 = fmaxf(0.f, fmaf((v0 - mu) * rstd, par[256 + col0],     par[512 + col0]));
                float o1 = fmaxf(0.f, fmaf((v1 - mu) * rstd, par[256 + col0 + 1], par[512 + col0 + 1]));
                if (PH == 0) {
                    __half2 hxv = __floats2half2_rn(o0, o1);
                    uint32_t hx = *reinterpret_cast<uint32_t*>(&hxv);
                    uint32_t off = (uint32_t)(col0 >> 6) * 128
                                 + (uint32_t)((((col0 >> 3) & 7) ^ (p & 7)) << 4)
                                 + (uint32_t)((col0 & 7) * 2);
                    *reinterpret_cast<uint32_t*>(smc + OFF_A + p * 512 + off) = hx;
                    if (r == 0)
                        *reinterpret_cast<uint32_t*>(g_h1halo + bid * 1024 + off) = hx;
                    if (r == 63)
                        *reinterpret_cast<uint32_t*>(g_h1halo + bid * 1024 + 512 + off) = hx;
                } else {
                    la = fmaf(o0, par[768 + col0], la);
                    la = fmaf(o1, par[768 + col0 + 1], la);
                }
            }
            lacc[mi][rh] = la;
        }

    if (PH == 1) {
        #pragma unroll
        for (int mi = 0; mi < 2; mi++)
            #pragma unroll
            for (int rh = 0; rh < 2; rh++) {
                float la = lacc[mi][rh];
                la += __shfl_xor_sync(0xffffffffu, la, 1);
                la += __shfl_xor_sync(0xffffffffu, la, 2);
                if ((lane & 3) == 0)
                    sLin[nw * 64 + mw * 32 + mi * 16 + rh * 8 + (lane >> 2)] = la;
            }
        __syncthreads();
        if (nw == 0 && (lane & 3) == 0) {
            #pragma unroll
            for (int mi = 0; mi < 2; mi++)
                #pragma unroll
                for (int rh = 0; rh < 2; rh++) {
                    int r = mw * 32 + mi * 16 + rh * 8 + (lane >> 2);
                    float t = sLin[r] + sLin[64 + r] + sLin[128 + r] + sLin[192 + r];
                    pred[mBase + r] = fmaxf(0.f, t + lbp[0]);
                }
        }
    }
}

// ---- fused conv0 + conv1 persistent kernel, in-kernel x conversion ----
__global__ __launch_bounds__(256, 2) void fused_conv_k(
    const float* __restrict__ x,
    const float* __restrict__ b1, const float* __restrict__ g1, const float* __restrict__ be1,
    const float* __restrict__ b2, const float* __restrict__ g2, const float* __restrict__ be2,
    const float* __restrict__ lw, const float* __restrict__ lbp, float* __restrict__ pred)
{
    extern __shared__ char smem[];
    const uint32_t sb0 = smem_u32(smem);
    const uint32_t tiles = (sb0 + 127) & ~127u;
    char* smc = smem + (tiles - sb0);
    float* sPar = (float*)(smc + OFF_PAR);
    float* sSum = (float*)(smc + OFF_SUM);
    float* sSq  = (float*)(smc + OFF_SQ);
    float* sLin = (float*)(smc + OFF_LIN);
    const uint32_t mbF = tiles + OFF_MBAR;
    const int tid = threadIdx.x, lane = tid & 31, warp = tid >> 5;
    const int mw = warp >> 2, nw = warp & 3;
    const int bid = blockIdx.x;
    const int mBase = bid * 64;
    const bool fix0 = ((mBase & 511) == 0);
    const bool fix2 = (((mBase + 64) & 511) == 0);

    int base = 0;
    if (tid == 0) base = g_flag[bid];

    sPar[tid] = b1[tid];        sPar[256 + tid] = g1[tid];
    sPar[512 + tid] = be1[tid]; sPar[768 + tid] = 0.f;
    sPar[1024 + tid] = b2[tid]; sPar[1280 + tid] = g2[tid];
    sPar[1536 + tid] = be2[tid]; sPar[1792 + tid] = lw[tid];
    if (tid == 0) {
        MBAR_INIT(mbF, 1); MBAR_INIT(mbF + 8, 1);
        MBAR_INIT(mbF + 16, 8); MBAR_INIT(mbF + 24, 8);
    }
    __syncthreads();

    // issue W1 chunks 0,1 (overlaps x conversion below)
    if (tid == 0) {
        #pragma unroll
        for (int j = 0; j < 2; j++) {
            MBAR_EXPECT(mbF + 8 * j, W_TILE);
            bulk_cp(tiles + j * W_TILE, g_w1s + (size_t)j * W_TILE, W_TILE, mbF + 8 * j);
        }
    }

    // convert own x rows (with halo) fp32 -> fp16 swizzled into persistent A region
    for (int it = tid; it < 66 * 32; it += 256) {
        int row = it >> 5, s = it & 31;
        bool zero = (row == 0 && fix0) || (row == 65 && fix2);
        float4 v0 = make_float4(0.f, 0.f, 0.f, 0.f), v1 = v0;
        if (!zero) {
            const float4* src = reinterpret_cast<const float4*>(
                x + (size_t)(mBase - 1 + row) * 256 + s * 8);
            v0 = src[0]; v1 = src[1];
        }
        __half2 a = __floats2half2_rn(v0.x, v0.y), b = __floats2half2_rn(v0.z, v0.w);
        __half2 c = __floats2half2_rn(v1.x, v1.y), d = __floats2half2_rn(v1.z, v1.w);
        uint4 o = make_uint4(*(uint32_t*)&a, *(uint32_t*)&b, *(uint32_t*)&c, *(uint32_t*)&d);
        *reinterpret_cast<uint4*>(smc + OFF_A + row * 512 + (s >> 3) * 128
            + (((s & 7) ^ (row & 7)) << 4)) = o;
    }
    __syncthreads();

    int pha[2] = {0, 0}, eph[2] = {0, 0};

    // phase 0: x -> h1 (h1 written to smem A region + 2 halo rows to gmem)
    conv_phase<0>(smc, tiles, g_w1s, mBase, bid, tid, lane, mw, nw,
                  pha, eph, sPar, sSum, sSq, sLin, pred, lbp);

    // publish halo rows; wait only for needed neighbors; fill p=0 / p=65
    __threadfence();
    __syncthreads();
    if (tid == 0) {
        atomicExch(&g_flag[bid], base + 1);
        const int tgt = base + 1;
        if (!fix0) while (ld_acq(&g_flag[bid - 1]) != tgt) __nanosleep(32);
        if (!fix2) while (ld_acq(&g_flag[bid + 1]) != tgt) __nanosleep(32);
    }
    __syncthreads();
    if (warp == 0) {
        uint4 v = make_uint4(0, 0, 0, 0);
        if (!fix0) v = *reinterpret_cast<const uint4*>(g_h1halo + (bid - 1) * 1024 + 512 + lane * 16);
        *reinterpret_cast<uint4*>(smc + OFF_A + lane * 16) = v;
    } else if (warp == 1) {
        uint4 v = make_uint4(0, 0, 0, 0);
        if (!fix2) v = *reinterpret_cast<const uint4*>(g_h1halo + (bid + 1) * 1024 + lane * 16);
        *reinterpret_cast<uint4*>(smc + OFF_A + 65 * 512 + lane * 16) = v;
    }
    __syncthreads();

    // phase 1: h1 -> pred
    conv_phase<1>(smc, tiles, g_w2s, mBase, bid, tid, lane, mw, nw,
                  pha, eph, sPar + 1024, sSum, sSq, sLin, pred, lbp);
}

// ---- rowmap + gather (unchanged, proven) ----
__global__ __launch_bounds__(512) void rowmap_k(const float* __restrict__ target, int L) {
    int b = blockIdx.x, s = threadIdx.x;
    int lane = s & 31, wp = s >> 5;
    int d = (int)rintf(target[b * 512 + s]);
    int v = d;
    #pragma unroll
    for (int o = 1; o < 32; o <<= 1) {
        int t = __shfl_up_sync(0xffffffffu, v, o);
        if (lane >= o) v += t;
    }
    __shared__ int wsum[16];
    if (lane == 31) wsum[wp] = v;
    __syncthreads();
    if (s < 16) {
        int w = wsum[s];
        #pragma unroll
        for (int o = 1; o < 16; o <<= 1) {
            int t = __shfl_up_sync(0x0000ffffu, w, o);
            if (s >= o) w += t;
        }
        wsum[s] = w;
    }
    __syncthreads();
    int end = v + (wp ? wsum[wp - 1] : 0);
    int start = end - d;
    int* rm = g_rowmap + (size_t)b * L;
    for (int l = s; l < L; l += 512) rm[l] = -1;
    __syncthreads();
    if (start < L) {
        int e = min(end, L);
        for (int l = start; l < e; ++l) rm[l] = s;
    }
}

__global__ __launch_bounds__(256) void gather_k(const float* __restrict__ x,
                                                float* __restrict__ out, int L) {
    int rowId = blockIdx.x * 4 + (threadIdx.x >> 6);
    if (rowId >= B_ * L) return;
    int t = threadIdx.x & 63;
    int b = rowId / L;
    int s = g_rowmap[rowId];
    float4 v = make_float4(0.f, 0.f, 0.f, 0.f);
    if (s >= 0)
        v = *reinterpret_cast<const float4*>(x + (size_t)((b << 9) + s) * D_ + (t << 2));
    *reinterpret_cast<float4*>(out + (size_t)rowId * D_ + (t << 2)) = v;
}

extern "C" void kernel_launch(void* const* d_in, const int* in_sizes, int n_in,
                              void* d_out, int out_size) {
    const float* x   = (const float*)d_in[0];
    const float* tgt = (const float*)d_in[1];
    const float* c1w = (const float*)d_in[2];
    const float* c1b = (const float*)d_in[3];
    const float* c2w = (const float*)d_in[4];
    const float* c2b = (const float*)d_in[5];
    const float* n1g = (const float*)d_in[6];
    const float* n1b = (const float*)d_in[7];
    const float* n2g = (const float*)d_in[8];
    const float* n2b = (const float*)d_in[9];
    const float* lw  = (const float*)d_in[10];
    const float* lb  = (const float*)d_in[11];

    float* out = (float*)d_out;
    int L = (out_size - B_ * S_) / (B_ * D_);
    float* pred = out + (size_t)B_ * L * D_;

    static cudaStream_t sHi = nullptr, sMid = nullptr, sLo = nullptr;
    static cudaEvent_t evF = nullptr, evW = nullptr, evH = nullptr, evJ = nullptr;
    if (sHi == nullptr) {
        int pLo, pHi;
        cudaDeviceGetStreamPriorityRange(&pLo, &pHi);
        cudaStreamCreateWithPriority(&sHi, cudaStreamNonBlocking, pHi);
        cudaStreamCreateWithPriority(&sMid, cudaStreamNonBlocking, pHi);
        cudaStreamCreateWithPriority(&sLo, cudaStreamNonBlocking, pLo);
        cudaEventCreateWithFlags(&evF, cudaEventDisableTiming);
        cudaEventCreateWithFlags(&evW, cudaEventDisableTiming);
        cudaEventCreateWithFlags(&evH, cudaEventDisableTiming);
        cudaEventCreateWithFlags(&evJ, cudaEventDisableTiming);
        cudaFuncSetAttribute(fused_conv_k, cudaFuncAttributeMaxDynamicSharedMemorySize, SMEM_TOTAL);
    }

    // fork
    cudaEventRecord(evF, 0);
    cudaStreamWaitEvent(sHi, evF, 0);
    cudaStreamWaitEvent(sMid, evF, 0);
    cudaStreamWaitEvent(sLo, evF, 0);

    // mid (high prio): weight prep — gates the conv
    cvt_w_k<<<2 * F_ * KK_ / 256, 256, 0, sMid>>>(c1w, c2w);
    cudaEventRecord(evW, sMid);

    // low priority: length regulator starts immediately at the fork
    rowmap_k<<<B_, 512, 0, sLo>>>(tgt, L);
    gather_k<<<(B_ * L + 3) / 4, 256, 0, sLo>>>(x, out, L);
    cudaEventRecord(evJ, sLo);

    // high priority: fused duration predictor
    cudaStreamWaitEvent(sHi, evW, 0);
    fused_conv_k<<<256, 256, SMEM_TOTAL, sHi>>>(x, c1b, n1g, n1b, c2b, n2g, n2b, lw, lb, pred);
    cudaEventRecord(evH, sHi);

    // join
    cudaStreamWaitEvent(0, evH, 0);
    cudaStreamWaitEvent(0, evJ, 0);
}